// round 8
// baseline (speedup 1.0000x reference)
#include <cuda_runtime.h>
#include <cuda_bf16.h>
#include <cstdint>

typedef unsigned long long ull;

#define TT 512
#define BB 32
#define DD 1280
#define TBD (TT*BB*DD)   // 20971520
#define RNC 128
#define RTPB 256
#define NW 8
// group decomposition: 4 groups x 32 CTAs; group owns 8 batches, CTA owns 40 cols
#define GRPS 4
#define CPG 32
#define BPG 8
#define JPC2 40
#define KQT (DD/4)       // 320 k-quads
#define QS (KQT/NW)      // 40 quads per warp
#define PFD 8

// -------- device scratch (no allocations allowed) --------
__device__ float g_xp[TBD];                     // x @ Wx^T + b
__device__ float g_h2[2][GRPS][KQT*BPG*4];      // h: [buf][g][(kq*8+b)*4+kk]  (40KB/grp)
__device__ unsigned g_flag[RNC*32];             // producer flags, 128B apart
__device__ float g_hlast_dummy[BB*DD];
__device__ __nv_bfloat16 g_xh[TBD];
__device__ __nv_bfloat16 g_xl[TBD];
__device__ __nv_bfloat16 g_wh[DD*DD];
__device__ __nv_bfloat16 g_wl[DD*DD];

// -------- packed f32x2 + memory helpers --------
__device__ __forceinline__ ull pack2(float lo, float hi){
  ull r; asm("mov.b64 %0, {%1, %2};" : "=l"(r) : "f"(lo), "f"(hi)); return r;
}
__device__ __forceinline__ float2 unpack2(ull v){
  float2 r; asm("mov.b64 {%0, %1}, %2;" : "=f"(r.x), "=f"(r.y) : "l"(v)); return r;
}
__device__ __forceinline__ void ffma2(ull& d, ull a, ull b){
  asm("fma.rn.f32x2 %0, %1, %2, %0;" : "+l"(d) : "l"(a), "l"(b));
}
__device__ __forceinline__ void ld_cg_v2u64(const void* p, ull& a, ull& b){
  asm volatile("ld.global.cg.v2.u64 {%0, %1}, [%2];" : "=l"(a), "=l"(b) : "l"(p));
}
__device__ __forceinline__ void st_cg_f32(float* p, float v){
  asm volatile("st.global.cg.f32 [%0], %1;" :: "l"(p), "f"(v) : "memory");
}
__device__ __forceinline__ unsigned ld_acq(const unsigned* p){
  unsigned v; asm volatile("ld.acquire.gpu.global.u32 %0, [%1];" : "=r"(v) : "l"(p)); return v;
}
__device__ __forceinline__ void st_rel(unsigned* p, unsigned v){
  asm volatile("st.release.gpu.global.u32 [%0], %1;" :: "l"(p), "r"(v) : "memory");
}
__device__ __forceinline__ float fast_tanh(float x){
  float e = __expf(2.0f * x);
  return 1.0f - __fdividef(2.0f, e + 1.0f);
}

// -------- baseline-PTX tensor-core helpers --------
__device__ __forceinline__ uint32_t smem_u32(const void* p){
  return (uint32_t)__cvta_generic_to_shared(p);
}
__device__ __forceinline__ void cp_async16(uint32_t dst, const void* src){
  asm volatile("cp.async.cg.shared.global [%0], [%1], 16;" :: "r"(dst), "l"(src));
}
__device__ __forceinline__ void cp_commit(){ asm volatile("cp.async.commit_group;" ::: "memory"); }
template<int N> __device__ __forceinline__ void cp_wait(){
  asm volatile("cp.async.wait_group %0;" :: "n"(N) : "memory");
}
__device__ __forceinline__ void ldsm_x4(uint32_t* r, uint32_t addr){
  asm volatile("ldmatrix.sync.aligned.m8n8.x4.shared.b16 {%0,%1,%2,%3}, [%4];"
    : "=r"(r[0]), "=r"(r[1]), "=r"(r[2]), "=r"(r[3]) : "r"(addr));
}
__device__ __forceinline__ void mma_bf16(float* c, const uint32_t* a,
                                         uint32_t b0, uint32_t b1){
  asm volatile(
    "mma.sync.aligned.m16n8k16.row.col.f32.bf16.bf16.f32 "
    "{%0,%1,%2,%3}, {%4,%5,%6,%7}, {%8,%9}, {%0,%1,%2,%3};"
    : "+f"(c[0]), "+f"(c[1]), "+f"(c[2]), "+f"(c[3])
    : "r"(a[0]), "r"(a[1]), "r"(a[2]), "r"(a[3]), "r"(b0), "r"(b1));
}

// ======================================================================
// Kernel A: split fp32 -> bf16 hi/lo pair
// ======================================================================
__global__ void convert_split(const float* __restrict__ src,
                              __nv_bfloat16* __restrict__ hi,
                              __nv_bfloat16* __restrict__ lo, size_t n)
{
  size_t stride = (size_t)gridDim.x * blockDim.x * 4;
  for (size_t i = ((size_t)blockIdx.x * blockDim.x + threadIdx.x) * 4; i < n; i += stride) {
    float4 v = *(const float4*)(src + i);
    __nv_bfloat162 h01 = __floats2bfloat162_rn(v.x, v.y);
    __nv_bfloat162 h23 = __floats2bfloat162_rn(v.z, v.w);
    __nv_bfloat162 l01 = __floats2bfloat162_rn(v.x - __bfloat162float(h01.x),
                                               v.y - __bfloat162float(h01.y));
    __nv_bfloat162 l23 = __floats2bfloat162_rn(v.z - __bfloat162float(h23.x),
                                               v.w - __bfloat162float(h23.y));
    *(__nv_bfloat162*)(hi + i)     = h01;
    *(__nv_bfloat162*)(hi + i + 2) = h23;
    *(__nv_bfloat162*)(lo + i)     = l01;
    *(__nv_bfloat162*)(lo + i + 2) = l23;
  }
}

// ======================================================================
// Kernel B: mma.sync bf16 GEMM (unchanged: 468us measured, tensor 56%)
// ======================================================================
#define GK 32
#define NCHUNK (DD/GK)
#define LDS_ROW 40
#define TILE_B (128*LDS_ROW*2)
#define STAGE_B (4*TILE_B)

__global__ __launch_bounds__(256) void gemm_bf16(const float* __restrict__ bias)
{
  extern __shared__ char dynsm[];
  const uint32_t tb = smem_u32(dynsm);

  const int tid = threadIdx.x;
  const int wid = tid >> 5, lane = tid & 31;
  const int wm = wid & 3, wn = wid >> 2;
  const int m0 = blockIdx.x * 128;
  const int n0 = blockIdx.y * 128;

  float acc[2][8][4];
  #pragma unroll
  for (int i = 0; i < 2; i++)
    #pragma unroll
    for (int j = 0; j < 8; j++)
      #pragma unroll
      for (int q = 0; q < 4; q++) acc[i][j][q] = 0.f;

  auto load_chunk = [&](int kc, int s) {
    const int k0 = kc * GK;
    const char* srcs[4] = {
      (const char*)(g_xh + (size_t)m0 * DD + k0),
      (const char*)(g_xl + (size_t)m0 * DD + k0),
      (const char*)(g_wh + (size_t)n0 * DD + k0),
      (const char*)(g_wl + (size_t)n0 * DD + k0) };
    #pragma unroll
    for (int tl = 0; tl < 4; ++tl) {
      uint32_t base = tb + s * STAGE_B + tl * TILE_B;
      const char* sp = srcs[tl];
      #pragma unroll
      for (int it = 0; it < 2; ++it) {
        int idx = tid + it * 256;
        int row = idx >> 2, c = idx & 3;
        cp_async16(base + row * (LDS_ROW * 2) + c * 16,
                   sp + (size_t)row * (DD * 2) + c * 16);
      }
    }
    cp_commit();
  };

  auto addrA = [&](int tile_off, int s, int row0, int ks) -> uint32_t {
    int row = row0 + (lane & 15);
    int col = ks + ((lane >> 4) << 3);
    return tb + s * STAGE_B + tile_off + (row * LDS_ROW + col) * 2;
  };
  auto addrB = [&](int tile_off, int s, int nrow0, int ks) -> uint32_t {
    int row = nrow0 + ((lane >> 4) << 3) + (lane & 7);
    int col = ks + (((lane >> 3) & 1) << 3);
    return tb + s * STAGE_B + tile_off + (row * LDS_ROW + col) * 2;
  };

  load_chunk(0, 0);
  load_chunk(1, 1);

  for (int kc = 0; kc < NCHUNK; ++kc) {
    const int s = kc & 1;
    if (kc >= NCHUNK - 2) cp_wait<0>(); else cp_wait<1>();
    __syncthreads();

    #pragma unroll
    for (int ks = 0; ks < GK; ks += 16) {
      uint32_t ah[2][4], al[2][4];
      #pragma unroll
      for (int mi = 0; mi < 2; ++mi) {
        ldsm_x4(ah[mi], addrA(0,        s, wm * 32 + mi * 16, ks));
        ldsm_x4(al[mi], addrA(TILE_B,   s, wm * 32 + mi * 16, ks));
      }
      #pragma unroll
      for (int nb = 0; nb < 4; ++nb) {
        uint32_t bh[4], bl[4];
        ldsm_x4(bh, addrB(2 * TILE_B, s, wn * 64 + nb * 16, ks));
        ldsm_x4(bl, addrB(3 * TILE_B, s, wn * 64 + nb * 16, ks));
        #pragma unroll
        for (int mi = 0; mi < 2; ++mi) {
          float* c0 = acc[mi][nb * 2];
          float* c1 = acc[mi][nb * 2 + 1];
          mma_bf16(c0, ah[mi], bh[0], bh[1]);
          mma_bf16(c1, ah[mi], bh[2], bh[3]);
          mma_bf16(c0, ah[mi], bl[0], bl[1]);
          mma_bf16(c1, ah[mi], bl[2], bl[3]);
          mma_bf16(c0, al[mi], bh[0], bh[1]);
          mma_bf16(c1, al[mi], bh[2], bh[3]);
        }
      }
    }
    __syncthreads();
    if (kc + 2 < NCHUNK) load_chunk(kc + 2, s);
  }

  const int mrow = lane >> 2, ncol = (lane & 3) * 2;
  #pragma unroll
  for (int mi = 0; mi < 2; ++mi) {
    #pragma unroll
    for (int ni = 0; ni < 8; ++ni) {
      int m = m0 + wm * 32 + mi * 16 + mrow;
      int n = n0 + wn * 64 + ni * 8 + ncol;
      float b0 = bias[n], b1 = bias[n + 1];
      *(float2*)&g_xp[(size_t)m * DD + n] =
          make_float2(acc[mi][ni][0] + b0, acc[mi][ni][1] + b1);
      *(float2*)&g_xp[(size_t)(m + 8) * DD + n] =
          make_float2(acc[mi][ni][2] + b0, acc[mi][ni][3] + b1);
    }
  }
}

// ======================================================================
// Kernel 0: reset flags + transpose h0 into group-interleaved layout
// ======================================================================
__global__ void init_state(const float* __restrict__ h0)
{
  int idx = blockIdx.x * blockDim.x + threadIdx.x;
  int stride = gridDim.x * blockDim.x;
  if (idx < RNC * 32) g_flag[idx] = 0;
  for (int i = idx; i < BB * DD; i += stride) {
    int gb = i / DD, k = i % DD;
    int g = gb >> 3, b = gb & 7;
    g_h2[0][g][((k >> 2) * BPG + b) * 4 + (k & 3)] = h0[i];
  }
}

// ======================================================================
// Kernel 2: recurrence, 4 independent groups of 32 CTAs.
// CTA (g,c): 40 cols, 8 batches. W slice 204.8KB in smem.
// R8 FIX: h-store index uses GLOBAL column (j0+ej), matching the global-k
// indexed layout that the read side and init_state use.
// ======================================================================
__global__ __launch_bounds__(RTPB, 1) void recurrence(
    const float* __restrict__ zseq, const float* __restrict__ Wh,
    float* __restrict__ out, float* __restrict__ hlast)
{
  extern __shared__ float sm[];
  float* ws   = sm;                    // [(kq*40 + j_rel)*4 + kk] : 204800 floats
  float* redb = sm + KQT * JPC2 * 4;   // [wid][lane][12] : 8*384 floats

  const int tid = threadIdx.x, bid = blockIdx.x;
  const int lane = tid & 31, wid = tid >> 5;
  const int g = bid >> 5;              // group 0..3
  const int c = bid & 31;              // CTA within group
  const int j0 = c * JPC2;             // absolute column base
  const int gb0 = g * BPG;             // absolute batch base

  // W slice -> smem (src-linear, coalesced global reads)
  {
    const float4* W4 = (const float4*)(Wh + (size_t)j0 * DD);
    float4* ws4 = (float4*)ws;
    for (int s = tid; s < JPC2 * KQT; s += RTPB) {
      int j_rel = s / KQT, kq = s % KQT;
      ws4[kq * JPC2 + j_rel] = W4[s];
    }
  }

  // compute mapping: lane -> (local batch, column subset)
  const int b    = lane >> 2;          // 0..7
  const int jsub = lane & 3;           // cols jsub*10 .. jsub*10+9

  // epilogue tasks: task = eb*40 + ej  (320 tasks over 256 threads)
  const int eb1 = tid / JPC2, ej1 = tid % JPC2;
  const int jg1 = j0 + ej1;                                 // GLOBAL column
  const int o1  = (gb0 + eb1) * DD + jg1;
  const int ha1 = ((jg1 >> 2) * BPG + eb1) * 4 + (jg1 & 3); // FIX: global col
  const int rs1 = (eb1 * 4 + ej1 / 10) * 12 + ej1 % 10;
  const bool has2 = (tid < BPG * JPC2 - RTPB);              // first 64 threads
  const int task2 = tid + RTPB;
  const int eb2 = task2 / JPC2, ej2 = task2 % JPC2;
  const int jg2 = j0 + ej2;
  const int o2  = (gb0 + eb2) * DD + jg2;
  const int ha2 = ((jg2 >> 2) * BPG + eb2) * 4 + (jg2 & 3); // FIX: global col
  const int rs2 = (eb2 * 4 + ej2 / 10) * 12 + ej2 % 10;

  __syncthreads();

  const int kq0 = wid * QS;
  // warp w's producers: group CTAs 4w..4w+3 (cols [160w, 160w+160))
  const unsigned* myflag = g_flag + (((g << 5) + (wid << 2) + (lane & 3)) << 5);

  size_t base = 0;
  float xp1 = __ldcs(&g_xp[o1]);
  float z1  = __ldcs(&zseq[o1]);
  float xp2 = has2 ? __ldcs(&g_xp[o2]) : 0.f;
  float z2  = has2 ? __ldcs(&zseq[o2]) : 0.f;

  for (int t = 0; t < TT; ++t) {
    const float* hc = g_h2[t & 1][g];
    float*       hn = g_h2[(t & 1) ^ 1][g];
    float sz1 = __fdividef(z1, 1.0f + __expf(-z1));
    float sz2 = has2 ? __fdividef(z2, 1.0f + __expf(-z2)) : 0.f;

    // ---- per-warp dataflow wait: my 4 producers have written h_t ----
    if (t > 0) {
      while (true) {
        unsigned v = ld_acq(myflag);
        if (__all_sync(0xffffffffu, v >= (unsigned)t)) break;
        __nanosleep(32);
      }
    }

    // ---- partials: 10 cols x 1 batch x 160 k per lane ----
    ull acc[10];
    #pragma unroll
    for (int j = 0; j < 10; ++j) acc[j] = 0ull;

    const char* hp = (const char*)hc + ((size_t)kq0 * BPG + b) * 16;  // +128B/quad
    ull h0r[PFD], h1r[PFD];
    #pragma unroll
    for (int d = 0; d < PFD; ++d) ld_cg_v2u64(hp + (size_t)d * 128, h0r[d], h1r[d]);
    #pragma unroll 8
    for (int q = 0; q < QS; ++q) {
      ull h0 = h0r[q & (PFD-1)], h1 = h1r[q & (PFD-1)];
      if (q + PFD < QS)
        ld_cg_v2u64(hp + (size_t)(q + PFD) * 128, h0r[q & (PFD-1)], h1r[q & (PFD-1)]);
      const ulonglong2* wq =
          (const ulonglong2*)(ws + ((size_t)(kq0 + q) * JPC2 + jsub * 10) * 4);
      #pragma unroll
      for (int j = 0; j < 10; ++j) {
        ulonglong2 wv = wq[j];     // LDS.128: 4 distinct addrs (banks 0,8,16,24)
        ffma2(acc[j], h0, wv.x);
        ffma2(acc[j], h1, wv.y);
      }
    }

    // ---- stage partials: redb[wid][lane][10] ----
    {
      float s[10];
      #pragma unroll
      for (int j = 0; j < 10; ++j) { float2 p = unpack2(acc[j]); s[j] = p.x + p.y; }
      float* rp = redb + wid * 384 + lane * 12;
      *(float4*)(rp + 0) = make_float4(s[0], s[1], s[2], s[3]);
      *(float4*)(rp + 4) = make_float4(s[4], s[5], s[6], s[7]);
      *(float2*)(rp + 8) = make_float2(s[8], s[9]);
    }
    __syncthreads();   // A: partials visible; hn overwrite safe (all warps passed polls)

    // ---- critical-path epilogue: reduce 8 warps, tanh, store h ----
    float hv1, hv2 = 0.f;
    {
      float s = 0.f;
      #pragma unroll
      for (int w = 0; w < NW; ++w) s += redb[w * 384 + rs1];
      hv1 = fast_tanh(xp1 + s);
      st_cg_f32(&hn[ha1], hv1);
    }
    if (has2) {
      float s = 0.f;
      #pragma unroll
      for (int w = 0; w < NW; ++w) s += redb[w * 384 + rs2];
      hv2 = fast_tanh(xp2 + s);
      st_cg_f32(&hn[ha2], hv2);
    }
    __syncthreads();   // B: hn stores issued, redb reads done

    // ---- publish ----
    if (tid == 0) st_rel(&g_flag[bid * 32], (unsigned)(t + 1));

    // ---- off-path: gated output, hlast, next-step prefetch ----
    out[base + o1] = hv1 * sz1;
    if (has2) out[base + o2] = hv2 * sz2;
    if (t == TT - 1) {
      hlast[o1] = hv1;
      if (has2) hlast[o2] = hv2;
    }
    base += (size_t)BB * DD;
    if (t + 1 < TT) {
      xp1 = __ldcs(&g_xp[base + o1]);
      z1  = __ldcs(&zseq[base + o1]);
      if (has2) { xp2 = __ldcs(&g_xp[base + o2]); z2 = __ldcs(&zseq[base + o2]); }
    }
  }
}

// ======================================================================
extern "C" void kernel_launch(void* const* d_in, const int* in_sizes, int n_in,
                              void* d_out, int out_size)
{
  const float* x    = (const float*)d_in[0];
  const float* z    = (const float*)d_in[1];
  const float* h0   = (const float*)d_in[2];
  const float* Wx   = (const float*)d_in[3];
  const float* Wh   = (const float*)d_in[4];
  const float* bias = (const float*)d_in[5];

  float* out = (float*)d_out;
  void* dummy = nullptr;
  cudaGetSymbolAddress(&dummy, g_hlast_dummy);
  float* hlast = (out_size >= (int)(TBD + BB * DD)) ? (out + TBD) : (float*)dummy;

  void *p_xh, *p_xl, *p_wh, *p_wl;
  cudaGetSymbolAddress(&p_xh, g_xh); cudaGetSymbolAddress(&p_xl, g_xl);
  cudaGetSymbolAddress(&p_wh, g_wh); cudaGetSymbolAddress(&p_wl, g_wl);

  const int rec_smem  = (KQT * JPC2 * 4 + NW * 384) * (int)sizeof(float); // 217088 B
  const int gemm_smem = 2 * STAGE_B;
  cudaFuncSetAttribute(recurrence, cudaFuncAttributeMaxDynamicSharedMemorySize, rec_smem);
  cudaFuncSetAttribute(gemm_bf16,  cudaFuncAttributeMaxDynamicSharedMemorySize, gemm_smem);

  init_state<<<40, 256>>>(h0);
  convert_split<<<2048, 256>>>(x,  (__nv_bfloat16*)p_xh, (__nv_bfloat16*)p_xl, (size_t)TBD);
  convert_split<<<512, 256>>>(Wx, (__nv_bfloat16*)p_wh, (__nv_bfloat16*)p_wl, (size_t)DD*DD);
  gemm_bf16<<<dim3(128, 10), 256, gemm_smem>>>(bias);
  recurrence<<<RNC, RTPB, rec_smem>>>(z, Wh, out, hlast);
}

// round 9
// speedup vs baseline: 1.4547x; 1.4547x over previous
#include <cuda_runtime.h>
#include <cuda_bf16.h>
#include <cstdint>

typedef unsigned long long ull;

#define TT 512
#define BB 32
#define DD 1280
#define TBD (TT*BB*DD)   // 20971520
#define RNC 128
#define RTPB 256
#define NW 8
// half decomposition: 2 halves x 64 CTAs; half owns 16 batches, CTA owns 20 cols
#define GRPS 2
#define CPG 64
#define BPG 16
#define JPC 20
#define KQT (DD/4)       // 320 k-quads
#define QS (KQT/NW)      // 40 quads per warp
#define PFD 8

// -------- device scratch (no allocations allowed) --------
__device__ float g_xp[TBD];                     // x @ Wx^T + b
__device__ float g_h2[2][GRPS][KQT*BPG*4];      // h: [buf][half][(kq*16+b)*4+kk] (80KB/half)
__device__ unsigned g_flag[RNC*32];             // producer flags, 128B apart
__device__ float g_hlast_dummy[BB*DD];
__device__ __nv_bfloat16 g_xh[TBD];
__device__ __nv_bfloat16 g_xl[TBD];
__device__ __nv_bfloat16 g_wh[DD*DD];
__device__ __nv_bfloat16 g_wl[DD*DD];

// -------- packed f32x2 + memory helpers --------
__device__ __forceinline__ ull pack2(float lo, float hi){
  ull r; asm("mov.b64 %0, {%1, %2};" : "=l"(r) : "f"(lo), "f"(hi)); return r;
}
__device__ __forceinline__ float2 unpack2(ull v){
  float2 r; asm("mov.b64 {%0, %1}, %2;" : "=f"(r.x), "=f"(r.y) : "l"(v)); return r;
}
__device__ __forceinline__ void ffma2(ull& d, ull a, ull b){
  asm("fma.rn.f32x2 %0, %1, %2, %0;" : "+l"(d) : "l"(a), "l"(b));
}
__device__ __forceinline__ void ld_cg_v2u64(const void* p, ull& a, ull& b){
  asm volatile("ld.global.cg.v2.u64 {%0, %1}, [%2];" : "=l"(a), "=l"(b) : "l"(p));
}
__device__ __forceinline__ void st_cg_f32(float* p, float v){
  asm volatile("st.global.cg.f32 [%0], %1;" :: "l"(p), "f"(v) : "memory");
}
__device__ __forceinline__ unsigned ld_acq(const unsigned* p){
  unsigned v; asm volatile("ld.acquire.gpu.global.u32 %0, [%1];" : "=r"(v) : "l"(p)); return v;
}
__device__ __forceinline__ void st_rel(unsigned* p, unsigned v){
  asm volatile("st.release.gpu.global.u32 [%0], %1;" :: "l"(p), "r"(v) : "memory");
}
__device__ __forceinline__ float fast_tanh(float x){
  float e = __expf(2.0f * x);
  return 1.0f - __fdividef(2.0f, e + 1.0f);
}

// -------- baseline-PTX tensor-core helpers --------
__device__ __forceinline__ uint32_t smem_u32(const void* p){
  return (uint32_t)__cvta_generic_to_shared(p);
}
__device__ __forceinline__ void cp_async16(uint32_t dst, const void* src){
  asm volatile("cp.async.cg.shared.global [%0], [%1], 16;" :: "r"(dst), "l"(src));
}
__device__ __forceinline__ void cp_commit(){ asm volatile("cp.async.commit_group;" ::: "memory"); }
template<int N> __device__ __forceinline__ void cp_wait(){
  asm volatile("cp.async.wait_group %0;" :: "n"(N) : "memory");
}
__device__ __forceinline__ void ldsm_x4(uint32_t* r, uint32_t addr){
  asm volatile("ldmatrix.sync.aligned.m8n8.x4.shared.b16 {%0,%1,%2,%3}, [%4];"
    : "=r"(r[0]), "=r"(r[1]), "=r"(r[2]), "=r"(r[3]) : "r"(addr));
}
__device__ __forceinline__ void mma_bf16(float* c, const uint32_t* a,
                                         uint32_t b0, uint32_t b1){
  asm volatile(
    "mma.sync.aligned.m16n8k16.row.col.f32.bf16.bf16.f32 "
    "{%0,%1,%2,%3}, {%4,%5,%6,%7}, {%8,%9}, {%0,%1,%2,%3};"
    : "+f"(c[0]), "+f"(c[1]), "+f"(c[2]), "+f"(c[3])
    : "r"(a[0]), "r"(a[1]), "r"(a[2]), "r"(a[3]), "r"(b0), "r"(b1));
}

// ======================================================================
// Kernel A: split fp32 -> bf16 hi/lo pair
// ======================================================================
__global__ void convert_split(const float* __restrict__ src,
                              __nv_bfloat16* __restrict__ hi,
                              __nv_bfloat16* __restrict__ lo, size_t n)
{
  size_t stride = (size_t)gridDim.x * blockDim.x * 4;
  for (size_t i = ((size_t)blockIdx.x * blockDim.x + threadIdx.x) * 4; i < n; i += stride) {
    float4 v = *(const float4*)(src + i);
    __nv_bfloat162 h01 = __floats2bfloat162_rn(v.x, v.y);
    __nv_bfloat162 h23 = __floats2bfloat162_rn(v.z, v.w);
    __nv_bfloat162 l01 = __floats2bfloat162_rn(v.x - __bfloat162float(h01.x),
                                               v.y - __bfloat162float(h01.y));
    __nv_bfloat162 l23 = __floats2bfloat162_rn(v.z - __bfloat162float(h23.x),
                                               v.w - __bfloat162float(h23.y));
    *(__nv_bfloat162*)(hi + i)     = h01;
    *(__nv_bfloat162*)(hi + i + 2) = h23;
    *(__nv_bfloat162*)(lo + i)     = l01;
    *(__nv_bfloat162*)(lo + i + 2) = l23;
  }
}

// ======================================================================
// Kernel B: mma.sync bf16 GEMM (unchanged: 468us measured, tensor 56%)
// ======================================================================
#define GK 32
#define NCHUNK (DD/GK)
#define LDS_ROW 40
#define TILE_B (128*LDS_ROW*2)
#define STAGE_B (4*TILE_B)

__global__ __launch_bounds__(256) void gemm_bf16(const float* __restrict__ bias)
{
  extern __shared__ char dynsm[];
  const uint32_t tb = smem_u32(dynsm);

  const int tid = threadIdx.x;
  const int wid = tid >> 5, lane = tid & 31;
  const int wm = wid & 3, wn = wid >> 2;
  const int m0 = blockIdx.x * 128;
  const int n0 = blockIdx.y * 128;

  float acc[2][8][4];
  #pragma unroll
  for (int i = 0; i < 2; i++)
    #pragma unroll
    for (int j = 0; j < 8; j++)
      #pragma unroll
      for (int q = 0; q < 4; q++) acc[i][j][q] = 0.f;

  auto load_chunk = [&](int kc, int s) {
    const int k0 = kc * GK;
    const char* srcs[4] = {
      (const char*)(g_xh + (size_t)m0 * DD + k0),
      (const char*)(g_xl + (size_t)m0 * DD + k0),
      (const char*)(g_wh + (size_t)n0 * DD + k0),
      (const char*)(g_wl + (size_t)n0 * DD + k0) };
    #pragma unroll
    for (int tl = 0; tl < 4; ++tl) {
      uint32_t base = tb + s * STAGE_B + tl * TILE_B;
      const char* sp = srcs[tl];
      #pragma unroll
      for (int it = 0; it < 2; ++it) {
        int idx = tid + it * 256;
        int row = idx >> 2, c = idx & 3;
        cp_async16(base + row * (LDS_ROW * 2) + c * 16,
                   sp + (size_t)row * (DD * 2) + c * 16);
      }
    }
    cp_commit();
  };

  auto addrA = [&](int tile_off, int s, int row0, int ks) -> uint32_t {
    int row = row0 + (lane & 15);
    int col = ks + ((lane >> 4) << 3);
    return tb + s * STAGE_B + tile_off + (row * LDS_ROW + col) * 2;
  };
  auto addrB = [&](int tile_off, int s, int nrow0, int ks) -> uint32_t {
    int row = nrow0 + ((lane >> 4) << 3) + (lane & 7);
    int col = ks + (((lane >> 3) & 1) << 3);
    return tb + s * STAGE_B + tile_off + (row * LDS_ROW + col) * 2;
  };

  load_chunk(0, 0);
  load_chunk(1, 1);

  for (int kc = 0; kc < NCHUNK; ++kc) {
    const int s = kc & 1;
    if (kc >= NCHUNK - 2) cp_wait<0>(); else cp_wait<1>();
    __syncthreads();

    #pragma unroll
    for (int ks = 0; ks < GK; ks += 16) {
      uint32_t ah[2][4], al[2][4];
      #pragma unroll
      for (int mi = 0; mi < 2; ++mi) {
        ldsm_x4(ah[mi], addrA(0,        s, wm * 32 + mi * 16, ks));
        ldsm_x4(al[mi], addrA(TILE_B,   s, wm * 32 + mi * 16, ks));
      }
      #pragma unroll
      for (int nb = 0; nb < 4; ++nb) {
        uint32_t bh[4], bl[4];
        ldsm_x4(bh, addrB(2 * TILE_B, s, wn * 64 + nb * 16, ks));
        ldsm_x4(bl, addrB(3 * TILE_B, s, wn * 64 + nb * 16, ks));
        #pragma unroll
        for (int mi = 0; mi < 2; ++mi) {
          float* c0 = acc[mi][nb * 2];
          float* c1 = acc[mi][nb * 2 + 1];
          mma_bf16(c0, ah[mi], bh[0], bh[1]);
          mma_bf16(c1, ah[mi], bh[2], bh[3]);
          mma_bf16(c0, ah[mi], bl[0], bl[1]);
          mma_bf16(c1, ah[mi], bl[2], bl[3]);
          mma_bf16(c0, al[mi], bh[0], bh[1]);
          mma_bf16(c1, al[mi], bh[2], bh[3]);
        }
      }
    }
    __syncthreads();
    if (kc + 2 < NCHUNK) load_chunk(kc + 2, s);
  }

  const int mrow = lane >> 2, ncol = (lane & 3) * 2;
  #pragma unroll
  for (int mi = 0; mi < 2; ++mi) {
    #pragma unroll
    for (int ni = 0; ni < 8; ++ni) {
      int m = m0 + wm * 32 + mi * 16 + mrow;
      int n = n0 + wn * 64 + ni * 8 + ncol;
      float b0 = bias[n], b1 = bias[n + 1];
      *(float2*)&g_xp[(size_t)m * DD + n] =
          make_float2(acc[mi][ni][0] + b0, acc[mi][ni][1] + b1);
      *(float2*)&g_xp[(size_t)(m + 8) * DD + n] =
          make_float2(acc[mi][ni][2] + b0, acc[mi][ni][3] + b1);
    }
  }
}

// ======================================================================
// Kernel 0: reset flags + transpose h0 into half-interleaved layout
// ======================================================================
__global__ void init_state(const float* __restrict__ h0)
{
  int idx = blockIdx.x * blockDim.x + threadIdx.x;
  int stride = gridDim.x * blockDim.x;
  if (idx < RNC * 32) g_flag[idx] = 0;
  for (int i = idx; i < BB * DD; i += stride) {
    int gb = i / DD, k = i % DD;
    int half = gb >> 4, b = gb & 15;
    g_h2[0][half][((k >> 2) * BPG + b) * 4 + (k & 3)] = h0[i];
  }
}

// ======================================================================
// Kernel 2: recurrence, 2 independent halves of 64 CTAs.
// CTA (half,c): 20 cols x 16 batches. W slice 102.4KB smem (L1 ~113KB left).
// lane = b*2 + jsub; warp = k-split (160 k); fan-in 8 producers/warp.
// Per-half NBUF=2 safe: every half CTA reads all 64 half producers/step.
// h-state indexed by GLOBAL column everywhere (R7 lesson).
// ======================================================================
__global__ __launch_bounds__(RTPB, 1) void recurrence(
    const float* __restrict__ zseq, const float* __restrict__ Wh,
    float* __restrict__ out, float* __restrict__ hlast)
{
  extern __shared__ float sm[];
  float* ws   = sm;                   // [(kq*20 + j_rel)*4 + kk] : 25600 floats
  float* redb = sm + KQT * JPC * 4;   // [wid][lane][12] : 8*384 floats

  const int tid = threadIdx.x, bid = blockIdx.x;
  const int lane = tid & 31, wid = tid >> 5;
  const int half = bid >> 6;           // 0..1
  const int c = bid & 63;              // CTA within half
  const int j0 = c * JPC;              // absolute column base
  const int gb0 = half * BPG;          // absolute batch base

  // W slice -> smem (src-linear, coalesced global reads)
  {
    const float4* W4 = (const float4*)(Wh + (size_t)j0 * DD);
    float4* ws4 = (float4*)ws;
    for (int s = tid; s < JPC * KQT; s += RTPB) {
      int j_rel = s / KQT, kq = s % KQT;
      ws4[kq * JPC + j_rel] = W4[s];
    }
  }

  // compute mapping: lane -> (local batch, column subset)
  const int b    = lane >> 1;          // 0..15
  const int jsub = lane & 1;           // cols jsub*10 .. jsub*10+9

  // epilogue tasks: task = eb*20 + ej (320 tasks over 256 threads)
  const int eb1 = tid / JPC, ej1 = tid % JPC;
  const int jg1 = j0 + ej1;                                  // GLOBAL column
  const int o1  = (gb0 + eb1) * DD + jg1;
  const int ha1 = ((jg1 >> 2) * BPG + eb1) * 4 + (jg1 & 3);
  const int rs1 = (eb1 * 2 + ej1 / 10) * 12 + ej1 % 10;
  const bool has2 = (tid < BPG * JPC - RTPB);                // first 64 threads
  const int task2 = tid + RTPB;
  const int eb2 = task2 / JPC, ej2 = task2 % JPC;
  const int jg2 = j0 + ej2;
  const int o2  = (gb0 + eb2) * DD + jg2;
  const int ha2 = ((jg2 >> 2) * BPG + eb2) * 4 + (jg2 & 3);
  const int rs2 = (eb2 * 2 + ej2 / 10) * 12 + ej2 % 10;

  __syncthreads();

  const int kq0 = wid * QS;
  // warp w's k-span [w*160, w*160+160) -> producers: half CTAs 8w..8w+7
  const unsigned* myflag = g_flag + (((half << 6) + (wid << 3) + (lane & 7)) << 5);

  size_t base = 0;
  float xp1 = __ldcs(&g_xp[o1]);
  float z1  = __ldcs(&zseq[o1]);
  float xp2 = has2 ? __ldcs(&g_xp[o2]) : 0.f;
  float z2  = has2 ? __ldcs(&zseq[o2]) : 0.f;

  for (int t = 0; t < TT; ++t) {
    const float* hc = g_h2[t & 1][half];
    float*       hn = g_h2[(t & 1) ^ 1][half];
    float sz1 = __fdividef(z1, 1.0f + __expf(-z1));
    float sz2 = has2 ? __fdividef(z2, 1.0f + __expf(-z2)) : 0.f;

    // ---- per-warp dataflow wait: my 8 producers have written h_t ----
    if (t > 0) {
      while (true) {
        unsigned v = ld_acq(myflag);
        if (__all_sync(0xffffffffu, v >= (unsigned)t)) break;
        __nanosleep(32);
      }
    }

    // ---- partials: 10 cols x 1 batch x 160 k per lane ----
    ull acc[10];
    #pragma unroll
    for (int j = 0; j < 10; ++j) acc[j] = 0ull;

    const char* hp = (const char*)hc + ((size_t)kq0 * BPG + b) * 16;  // +256B/quad
    ull h0r[PFD], h1r[PFD];
    #pragma unroll
    for (int d = 0; d < PFD; ++d) ld_cg_v2u64(hp + (size_t)d * 256, h0r[d], h1r[d]);
    #pragma unroll 8
    for (int q = 0; q < QS; ++q) {
      ull h0 = h0r[q & (PFD-1)], h1 = h1r[q & (PFD-1)];
      if (q + PFD < QS)
        ld_cg_v2u64(hp + (size_t)(q + PFD) * 256, h0r[q & (PFD-1)], h1r[q & (PFD-1)]);
      const ulonglong2* wq =
          (const ulonglong2*)(ws + ((size_t)(kq0 + q) * JPC + jsub * 10) * 4);
      #pragma unroll
      for (int j = 0; j < 10; ++j) {
        ulonglong2 wv = wq[j];     // LDS.128: 2 distinct 16B addrs, conflict-free
        ffma2(acc[j], h0, wv.x);
        ffma2(acc[j], h1, wv.y);
      }
    }

    // ---- stage partials: redb[wid][lane][10] ----
    {
      float s[10];
      #pragma unroll
      for (int j = 0; j < 10; ++j) { float2 p = unpack2(acc[j]); s[j] = p.x + p.y; }
      float* rp = redb + wid * 384 + lane * 12;
      *(float4*)(rp + 0) = make_float4(s[0], s[1], s[2], s[3]);
      *(float4*)(rp + 4) = make_float4(s[4], s[5], s[6], s[7]);
      *(float2*)(rp + 8) = make_float2(s[8], s[9]);
    }
    __syncthreads();   // A: partials visible; hn overwrite safe (all warps passed polls)

    // ---- critical-path epilogue: reduce 8 warps, tanh, store h ----
    float hv1, hv2 = 0.f;
    {
      float s = 0.f;
      #pragma unroll
      for (int w = 0; w < NW; ++w) s += redb[w * 384 + rs1];
      hv1 = fast_tanh(xp1 + s);
      st_cg_f32(&hn[ha1], hv1);
    }
    if (has2) {
      float s = 0.f;
      #pragma unroll
      for (int w = 0; w < NW; ++w) s += redb[w * 384 + rs2];
      hv2 = fast_tanh(xp2 + s);
      st_cg_f32(&hn[ha2], hv2);
    }
    __syncthreads();   // B: hn stores issued, redb reads done

    // ---- publish ----
    if (tid == 0) st_rel(&g_flag[bid * 32], (unsigned)(t + 1));

    // ---- off-path: gated output, hlast, next-step prefetch ----
    out[base + o1] = hv1 * sz1;
    if (has2) out[base + o2] = hv2 * sz2;
    if (t == TT - 1) {
      hlast[o1] = hv1;
      if (has2) hlast[o2] = hv2;
    }
    base += (size_t)BB * DD;
    if (t + 1 < TT) {
      xp1 = __ldcs(&g_xp[base + o1]);
      z1  = __ldcs(&zseq[base + o1]);
      if (has2) { xp2 = __ldcs(&g_xp[base + o2]); z2 = __ldcs(&zseq[base + o2]); }
    }
  }
}

// ======================================================================
extern "C" void kernel_launch(void* const* d_in, const int* in_sizes, int n_in,
                              void* d_out, int out_size)
{
  const float* x    = (const float*)d_in[0];
  const float* z    = (const float*)d_in[1];
  const float* h0   = (const float*)d_in[2];
  const float* Wx   = (const float*)d_in[3];
  const float* Wh   = (const float*)d_in[4];
  const float* bias = (const float*)d_in[5];

  float* out = (float*)d_out;
  void* dummy = nullptr;
  cudaGetSymbolAddress(&dummy, g_hlast_dummy);
  float* hlast = (out_size >= (int)(TBD + BB * DD)) ? (out + TBD) : (float*)dummy;

  void *p_xh, *p_xl, *p_wh, *p_wl;
  cudaGetSymbolAddress(&p_xh, g_xh); cudaGetSymbolAddress(&p_xl, g_xl);
  cudaGetSymbolAddress(&p_wh, g_wh); cudaGetSymbolAddress(&p_wl, g_wl);

  const int rec_smem  = (KQT * JPC * 4 + NW * 384) * (int)sizeof(float); // 114688 B
  const int gemm_smem = 2 * STAGE_B;
  cudaFuncSetAttribute(recurrence, cudaFuncAttributeMaxDynamicSharedMemorySize, rec_smem);
  cudaFuncSetAttribute(gemm_bf16,  cudaFuncAttributeMaxDynamicSharedMemorySize, gemm_smem);

  init_state<<<40, 256>>>(h0);
  convert_split<<<2048, 256>>>(x,  (__nv_bfloat16*)p_xh, (__nv_bfloat16*)p_xl, (size_t)TBD);
  convert_split<<<512, 256>>>(Wx, (__nv_bfloat16*)p_wh, (__nv_bfloat16*)p_wl, (size_t)DD*DD);
  gemm_bf16<<<dim3(128, 10), 256, gemm_smem>>>(bias);
  recurrence<<<RNC, RTPB, rec_smem>>>(z, Wh, out, hlast);
}

// round 12
// speedup vs baseline: 2.1300x; 1.4641x over previous
#include <cuda_runtime.h>
#include <cuda_bf16.h>
#include <cstdint>

typedef unsigned long long ull;

#define TT 512
#define BB 32
#define DD 1280
#define TBD (TT*BB*DD)   // 20971520
#define RNC 128
#define RTPB 256
#define NW 8
// half decomposition: 2 halves x 64 CTAs; half owns 16 batches, CTA owns 20 cols
#define GRPS 2
#define CPG 64
#define BPG 16
#define JPC 20
#define KPT 640          // k-pairs total (1280/2)
#define NFRAG 7680       // 80 ksteps * 3 ntiles * 32 lanes

// -------- device scratch (no allocations allowed) --------
__device__ float g_xp[TBD];                      // x @ Wx^T + b
__device__ uint2 g_hb[2][GRPS][KPT*BPG];         // h bf16 split: [buf][half][kp*16+b] = {hi_pair, lo_pair}
__device__ unsigned g_flag[RNC*32];              // producer flags, 128B apart
__device__ float g_hlast_dummy[BB*DD];
__device__ __nv_bfloat16 g_xh[TBD];
__device__ __nv_bfloat16 g_xl[TBD];
__device__ __nv_bfloat16 g_wh[DD*DD];
__device__ __nv_bfloat16 g_wl[DD*DD];

// -------- helpers --------
__device__ __forceinline__ unsigned ld_acq(const unsigned* p){
  unsigned v; asm volatile("ld.acquire.gpu.global.u32 %0, [%1];" : "=r"(v) : "l"(p)); return v;
}
__device__ __forceinline__ void st_rel(unsigned* p, unsigned v){
  asm volatile("st.release.gpu.global.u32 [%0], %1;" :: "l"(p), "r"(v) : "memory");
}
__device__ __forceinline__ uint2 ld_cg_u2(const uint2* p){
  uint2 r; asm volatile("ld.global.cg.v2.u32 {%0,%1}, [%2];" : "=r"(r.x), "=r"(r.y) : "l"(p)); return r;
}
__device__ __forceinline__ void st_cg_u2(uint2* p, uint2 v){
  asm volatile("st.global.cg.v2.u32 [%0], {%1,%2};" :: "l"(p), "r"(v.x), "r"(v.y) : "memory");
}
__device__ __forceinline__ float fast_tanh(float x){
  float e = __expf(2.0f * x);
  return 1.0f - __fdividef(2.0f, e + 1.0f);
}
__device__ __forceinline__ uint32_t bf2_u32(__nv_bfloat162 v){
  uint32_t r; memcpy(&r, &v, 4); return r;
}
__device__ __forceinline__ uint32_t smem_u32(const void* p){
  return (uint32_t)__cvta_generic_to_shared(p);
}
__device__ __forceinline__ void cp_async16(uint32_t dst, const void* src){
  asm volatile("cp.async.cg.shared.global [%0], [%1], 16;" :: "r"(dst), "l"(src));
}
__device__ __forceinline__ void cp_commit(){ asm volatile("cp.async.commit_group;" ::: "memory"); }
template<int N> __device__ __forceinline__ void cp_wait(){
  asm volatile("cp.async.wait_group %0;" :: "n"(N) : "memory");
}
__device__ __forceinline__ void ldsm_x4(uint32_t* r, uint32_t addr){
  asm volatile("ldmatrix.sync.aligned.m8n8.x4.shared.b16 {%0,%1,%2,%3}, [%4];"
    : "=r"(r[0]), "=r"(r[1]), "=r"(r[2]), "=r"(r[3]) : "r"(addr));
}
__device__ __forceinline__ void mma_bf16(float* c, const uint32_t* a,
                                         uint32_t b0, uint32_t b1){
  asm volatile(
    "mma.sync.aligned.m16n8k16.row.col.f32.bf16.bf16.f32 "
    "{%0,%1,%2,%3}, {%4,%5,%6,%7}, {%8,%9}, {%0,%1,%2,%3};"
    : "+f"(c[0]), "+f"(c[1]), "+f"(c[2]), "+f"(c[3])
    : "r"(a[0]), "r"(a[1]), "r"(a[2]), "r"(a[3]), "r"(b0), "r"(b1));
}

// ======================================================================
// Kernel A: split fp32 -> bf16 hi/lo pair (for GEMM)
// ======================================================================
__global__ void convert_split(const float* __restrict__ src,
                              __nv_bfloat16* __restrict__ hi,
                              __nv_bfloat16* __restrict__ lo, size_t n)
{
  size_t stride = (size_t)gridDim.x * blockDim.x * 4;
  for (size_t i = ((size_t)blockIdx.x * blockDim.x + threadIdx.x) * 4; i < n; i += stride) {
    float4 v = *(const float4*)(src + i);
    __nv_bfloat162 h01 = __floats2bfloat162_rn(v.x, v.y);
    __nv_bfloat162 h23 = __floats2bfloat162_rn(v.z, v.w);
    __nv_bfloat162 l01 = __floats2bfloat162_rn(v.x - __bfloat162float(h01.x),
                                               v.y - __bfloat162float(h01.y));
    __nv_bfloat162 l23 = __floats2bfloat162_rn(v.z - __bfloat162float(h23.x),
                                               v.w - __bfloat162float(h23.y));
    *(__nv_bfloat162*)(hi + i)     = h01;
    *(__nv_bfloat162*)(hi + i + 2) = h23;
    *(__nv_bfloat162*)(lo + i)     = l01;
    *(__nv_bfloat162*)(lo + i + 2) = l23;
  }
}

// ======================================================================
// Kernel B: mma.sync bf16 GEMM (unchanged: 468us measured, tensor 56%)
// ======================================================================
#define GK 32
#define NCHUNK (DD/GK)
#define LDS_ROW 40
#define TILE_B (128*LDS_ROW*2)
#define STAGE_B (4*TILE_B)

__global__ __launch_bounds__(256) void gemm_bf16(const float* __restrict__ bias)
{
  extern __shared__ char dynsm[];
  const uint32_t tb = smem_u32(dynsm);

  const int tid = threadIdx.x;
  const int wid = tid >> 5, lane = tid & 31;
  const int wm = wid & 3, wn = wid >> 2;
  const int m0 = blockIdx.x * 128;
  const int n0 = blockIdx.y * 128;

  float acc[2][8][4];
  #pragma unroll
  for (int i = 0; i < 2; i++)
    #pragma unroll
    for (int j = 0; j < 8; j++)
      #pragma unroll
      for (int q = 0; q < 4; q++) acc[i][j][q] = 0.f;

  auto load_chunk = [&](int kc, int s) {
    const int k0 = kc * GK;
    const char* srcs[4] = {
      (const char*)(g_xh + (size_t)m0 * DD + k0),
      (const char*)(g_xl + (size_t)m0 * DD + k0),
      (const char*)(g_wh + (size_t)n0 * DD + k0),
      (const char*)(g_wl + (size_t)n0 * DD + k0) };
    #pragma unroll
    for (int tl = 0; tl < 4; ++tl) {
      uint32_t base = tb + s * STAGE_B + tl * TILE_B;
      const char* sp = srcs[tl];
      #pragma unroll
      for (int it = 0; it < 2; ++it) {
        int idx = tid + it * 256;
        int row = idx >> 2, c = idx & 3;
        cp_async16(base + row * (LDS_ROW * 2) + c * 16,
                   sp + (size_t)row * (DD * 2) + c * 16);
      }
    }
    cp_commit();
  };

  auto addrA = [&](int tile_off, int s, int row0, int ks) -> uint32_t {
    int row = row0 + (lane & 15);
    int col = ks + ((lane >> 4) << 3);
    return tb + s * STAGE_B + tile_off + (row * LDS_ROW + col) * 2;
  };
  auto addrB = [&](int tile_off, int s, int nrow0, int ks) -> uint32_t {
    int row = nrow0 + ((lane >> 4) << 3) + (lane & 7);
    int col = ks + (((lane >> 3) & 1) << 3);
    return tb + s * STAGE_B + tile_off + (row * LDS_ROW + col) * 2;
  };

  load_chunk(0, 0);
  load_chunk(1, 1);

  for (int kc = 0; kc < NCHUNK; ++kc) {
    const int s = kc & 1;
    if (kc >= NCHUNK - 2) cp_wait<0>(); else cp_wait<1>();
    __syncthreads();

    #pragma unroll
    for (int ks = 0; ks < GK; ks += 16) {
      uint32_t ah[2][4], al[2][4];
      #pragma unroll
      for (int mi = 0; mi < 2; ++mi) {
        ldsm_x4(ah[mi], addrA(0,        s, wm * 32 + mi * 16, ks));
        ldsm_x4(al[mi], addrA(TILE_B,   s, wm * 32 + mi * 16, ks));
      }
      #pragma unroll
      for (int nb = 0; nb < 4; ++nb) {
        uint32_t bh[4], bl[4];
        ldsm_x4(bh, addrB(2 * TILE_B, s, wn * 64 + nb * 16, ks));
        ldsm_x4(bl, addrB(3 * TILE_B, s, wn * 64 + nb * 16, ks));
        #pragma unroll
        for (int mi = 0; mi < 2; ++mi) {
          float* c0 = acc[mi][nb * 2];
          float* c1 = acc[mi][nb * 2 + 1];
          mma_bf16(c0, ah[mi], bh[0], bh[1]);
          mma_bf16(c1, ah[mi], bh[2], bh[3]);
          mma_bf16(c0, ah[mi], bl[0], bl[1]);
          mma_bf16(c1, ah[mi], bl[2], bl[3]);
          mma_bf16(c0, al[mi], bh[0], bh[1]);
          mma_bf16(c1, al[mi], bh[2], bh[3]);
        }
      }
    }
    __syncthreads();
    if (kc + 2 < NCHUNK) load_chunk(kc + 2, s);
  }

  const int mrow = lane >> 2, ncol = (lane & 3) * 2;
  #pragma unroll
  for (int mi = 0; mi < 2; ++mi) {
    #pragma unroll
    for (int ni = 0; ni < 8; ++ni) {
      int m = m0 + wm * 32 + mi * 16 + mrow;
      int n = n0 + wn * 64 + ni * 8 + ncol;
      float b0 = bias[n], b1 = bias[n + 1];
      *(float2*)&g_xp[(size_t)m * DD + n] =
          make_float2(acc[mi][ni][0] + b0, acc[mi][ni][1] + b1);
      *(float2*)&g_xp[(size_t)(m + 8) * DD + n] =
          make_float2(acc[mi][ni][2] + b0, acc[mi][ni][3] + b1);
    }
  }
}

// ======================================================================
// Kernel 0: reset flags + h0 -> bf16 hi/lo pair layout
// ======================================================================
__global__ void init_state(const float* __restrict__ h0)
{
  int idx = blockIdx.x * blockDim.x + threadIdx.x;
  int stride = gridDim.x * blockDim.x;
  if (idx < RNC * 32) g_flag[idx] = 0;
  for (int i = idx; i < BB * KPT; i += stride) {
    int gb = i / KPT, kp = i % KPT;
    int half = gb >> 4, b = gb & 15;
    float v0 = h0[gb * DD + 2*kp], v1 = h0[gb * DD + 2*kp + 1];
    __nv_bfloat162 hi = __floats2bfloat162_rn(v0, v1);
    __nv_bfloat162 lo = __floats2bfloat162_rn(v0 - __bfloat162float(hi.x),
                                              v1 - __bfloat162float(hi.y));
    g_hb[0][half][kp * BPG + b] = make_uint2(bf2_u32(hi), bf2_u32(lo));
  }
}

// ======================================================================
// Kernel 2: recurrence on TENSOR CORES. 2 halves x 64 CTAs.
// CTA: out[16 batch x 20 col] = h[16x1280] . W[20x1280]^T via m16n8k16,
// 3-product bf16 split (hh + h*lo + lo*h). Warp w: k in [160w,160w+160).
// W pre-formatted as per-lane B-fragments in smem (one LDS.128 / mma trio).
// A-fragments LDG'd straight from L2 in fragment layout (no smem staging).
// ======================================================================
__global__ __launch_bounds__(RTPB, 1) void recurrence(
    const float* __restrict__ zseq, const float* __restrict__ Wh,
    float* __restrict__ out, float* __restrict__ hlast)
{
  extern __shared__ char sm[];
  uint4* wfrag = (uint4*)sm;                       // [NFRAG] = 122880 B
  float* redb  = (float*)(sm + NFRAG * 16);        // [wid][lane][12] = 12288 B

  const int tid = threadIdx.x, bid = blockIdx.x;
  const int lane = tid & 31, wid = tid >> 5;
  const int half = bid >> 6;            // 0..1
  const int c = bid & 63;               // CTA within half
  const int j0 = c * JPC;               // absolute column base
  const int gb0 = half * BPG;           // absolute batch base
  const int g = lane >> 2, tg = lane & 3;

  // ---- build W B-fragments (hi/lo) in smem, one-time ----
  for (int idx = tid; idx < NFRAG; idx += RTPB) {
    int ksg = idx / 96;                 // global k-step 0..79 (k = 16*ksg)
    int rem = idx % 96;
    int nt = rem >> 5, l = rem & 31;
    int lg = l >> 2, ltg = l & 3;
    int nl = nt * 8 + lg;               // local col 0..23
    uint32_t b0h = 0, b1h = 0, b0l = 0, b1l = 0;
    if (nl < JPC) {
      const float* wr = Wh + (size_t)(j0 + nl) * DD + ksg * 16 + 2 * ltg;
      float w0 = wr[0], w1 = wr[1], w8 = wr[8], w9 = wr[9];
      __nv_bfloat162 h01 = __floats2bfloat162_rn(w0, w1);
      __nv_bfloat162 h89 = __floats2bfloat162_rn(w8, w9);
      __nv_bfloat162 l01 = __floats2bfloat162_rn(w0 - __bfloat162float(h01.x),
                                                 w1 - __bfloat162float(h01.y));
      __nv_bfloat162 l89 = __floats2bfloat162_rn(w8 - __bfloat162float(h89.x),
                                                 w9 - __bfloat162float(h89.y));
      b0h = bf2_u32(h01); b1h = bf2_u32(h89);
      b0l = bf2_u32(l01); b1l = bf2_u32(l89);
    }
    wfrag[idx] = make_uint4(b0h, b1h, b0l, b1l);
  }

  // ---- epilogue pair-task mapping: 160 tasks (b, col-pair) ----
  const bool active = (tid < BPG * JPC / 2);       // 160 threads
  const int eb = tid / (JPC/2), jp = tid % (JPC/2);  // batch 0..15, pair 0..9
  const int jg = j0 + 2 * jp;                       // global even column
  const int oidx = (gb0 + eb) * DD + jg;            // out/xp/z offset (float2)
  const int kpg = j0 / 2 + jp;                      // GLOBAL k-pair index
  // redb source: nt = (2jp)/8, lane = (eb%8)*4 + ((2jp)%8)/2, reg = 2*(eb/8)
  const int ent = (2 * jp) >> 3;
  const int elane = (eb & 7) * 4 + (((2 * jp) & 7) >> 1);
  const int ereg = 2 * (eb >> 3);
  const int rs0 = elane * 12 + ent * 4 + ereg;      // col jg ; rs0+1 = col jg+1

  __syncthreads();

  // warp w's producers: half CTAs 8w..8w+7 (kp span [80w, 80w+80))
  const unsigned* myflag = g_flag + (((half << 6) + (wid << 3) + (lane & 7)) << 5);
  const int kb = wid * 80;              // warp's base k-pair

  size_t base = 0;
  float2 xp = active ? *(const float2*)&g_xp[oidx] : make_float2(0.f, 0.f);
  float2 zz = active ? *(const float2*)&zseq[oidx] : make_float2(0.f, 0.f);

  for (int t = 0; t < TT; ++t) {
    const uint2* hb = g_hb[t & 1][half];
    uint2*       hn = g_hb[(t & 1) ^ 1][half];
    float sz0 = __fdividef(zz.x, 1.0f + __expf(-zz.x));
    float sz1 = __fdividef(zz.y, 1.0f + __expf(-zz.y));

    // ---- per-warp dataflow wait: my 8 producers have written h_t ----
    if (t > 0) {
      while (true) {
        unsigned v = ld_acq(myflag);
        if (__all_sync(0xffffffffu, v >= (unsigned)t)) break;
        __nanosleep(32);
      }
    }

    // ---- tensor-core partials: 10 k-steps x 3 n-tiles x 3 split-products ----
    float acc[3][4];
    #pragma unroll
    for (int nt = 0; nt < 3; ++nt)
      #pragma unroll
      for (int r = 0; r < 4; ++r) acc[nt][r] = 0.f;

    // A-fragment loads (double-buffered): lane holds rows (g, g+8), k-pairs (tg, tg+4)
    uint2 a0, a1, a2, a3, n0, n1, n2, n3;
    {
      const uint2* p = hb + (kb + tg) * BPG;
      a0 = ld_cg_u2(p + g);  a1 = ld_cg_u2(p + g + 8);
      a2 = ld_cg_u2(p + 4 * BPG + g); a3 = ld_cg_u2(p + 4 * BPG + g + 8);
    }
    #pragma unroll
    for (int ks = 0; ks < 10; ++ks) {
      if (ks + 1 < 10) {
        const uint2* p = hb + (kb + 8 * (ks + 1) + tg) * BPG;
        n0 = ld_cg_u2(p + g);  n1 = ld_cg_u2(p + g + 8);
        n2 = ld_cg_u2(p + 4 * BPG + g); n3 = ld_cg_u2(p + 4 * BPG + g + 8);
      }
      uint32_t Ahi[4] = {a0.x, a1.x, a2.x, a3.x};
      uint32_t Alo[4] = {a0.y, a1.y, a2.y, a3.y};
      const uint4* wf = wfrag + ((wid * 10 + ks) * 3) * 32 + lane;
      uint4 w0 = wf[0], w1 = wf[32], w2 = wf[64];
      // interleave splits across n-tiles (independent accs hide RAW)
      mma_bf16(acc[0], Ahi, w0.x, w0.y);
      mma_bf16(acc[1], Ahi, w1.x, w1.y);
      mma_bf16(acc[2], Ahi, w2.x, w2.y);
      mma_bf16(acc[0], Ahi, w0.z, w0.w);
      mma_bf16(acc[1], Ahi, w1.z, w1.w);
      mma_bf16(acc[2], Ahi, w2.z, w2.w);
      mma_bf16(acc[0], Alo, w0.x, w0.y);
      mma_bf16(acc[1], Alo, w1.x, w1.y);
      mma_bf16(acc[2], Alo, w2.x, w2.y);
      a0 = n0; a1 = n1; a2 = n2; a3 = n3;
    }

    // ---- stage partials: redb[wid][lane][nt*4+r] ----
    {
      float* rp = redb + wid * 384 + lane * 12;
      #pragma unroll
      for (int nt = 0; nt < 3; ++nt)
        *(float4*)(rp + nt * 4) = make_float4(acc[nt][0], acc[nt][1],
                                              acc[nt][2], acc[nt][3]);
    }
    __syncthreads();   // A: partials visible; all warps passed polls => hn overwrite safe

    // ---- epilogue: reduce 8 warps, tanh, split h to bf16 pair, store ----
    float hv0 = 0.f, hv1 = 0.f;
    if (active) {
      float s0 = 0.f, s1 = 0.f;
      #pragma unroll
      for (int w = 0; w < NW; ++w) {
        const float* rb = redb + w * 384;
        s0 += rb[rs0]; s1 += rb[rs0 + 1];
      }
      hv0 = fast_tanh(xp.x + s0);
      hv1 = fast_tanh(xp.y + s1);
      __nv_bfloat162 hi = __floats2bfloat162_rn(hv0, hv1);
      __nv_bfloat162 lo = __floats2bfloat162_rn(hv0 - __bfloat162float(hi.x),
                                                hv1 - __bfloat162float(hi.y));
      st_cg_u2(&hn[kpg * BPG + eb], make_uint2(bf2_u32(hi), bf2_u32(lo)));
    }
    __syncthreads();   // B: hn stores issued, redb reads done

    // ---- publish ----
    if (tid == 0) st_rel(&g_flag[bid * 32], (unsigned)(t + 1));

    // ---- off-path: gated output, hlast, next-step prefetch ----
    if (active) {
      *(float2*)&out[base + oidx] = make_float2(hv0 * sz0, hv1 * sz1);
      if (t == TT - 1) *(float2*)&hlast[oidx] = make_float2(hv0, hv1);
    }
    base += (size_t)BB * DD;
    if (active && t + 1 < TT) {
      xp = *(const float2*)&g_xp[base + oidx];
      zz = *(const float2*)&zseq[base + oidx];
    }
  }
}

// ======================================================================
extern "C" void kernel_launch(void* const* d_in, const int* in_sizes, int n_in,
                              void* d_out, int out_size)
{
  const float* x    = (const float*)d_in[0];
  const float* z    = (const float*)d_in[1];
  const float* h0   = (const float*)d_in[2];
  const float* Wx   = (const float*)d_in[3];
  const float* Wh   = (const float*)d_in[4];
  const float* bias = (const float*)d_in[5];

  float* out = (float*)d_out;
  void* dummy = nullptr;
  cudaGetSymbolAddress(&dummy, g_hlast_dummy);
  float* hlast = (out_size >= (int)(TBD + BB * DD)) ? (out + TBD) : (float*)dummy;

  void *p_xh, *p_xl, *p_wh, *p_wl;
  cudaGetSymbolAddress(&p_xh, g_xh); cudaGetSymbolAddress(&p_xl, g_xl);
  cudaGetSymbolAddress(&p_wh, g_wh); cudaGetSymbolAddress(&p_wl, g_wl);

  const int rec_smem  = NFRAG * 16 + NW * 384 * (int)sizeof(float);  // 135168 B
  const int gemm_smem = 2 * STAGE_B;
  cudaFuncSetAttribute(recurrence, cudaFuncAttributeMaxDynamicSharedMemorySize, rec_smem);
  cudaFuncSetAttribute(gemm_bf16,  cudaFuncAttributeMaxDynamicSharedMemorySize, gemm_smem);

  init_state<<<40, 256>>>(h0);
  convert_split<<<2048, 256>>>(x,  (__nv_bfloat16*)p_xh, (__nv_bfloat16*)p_xl, (size_t)TBD);
  convert_split<<<512, 256>>>(Wx, (__nv_bfloat16*)p_wh, (__nv_bfloat16*)p_wl, (size_t)DD*DD);
  gemm_bf16<<<dim3(128, 10), 256, gemm_smem>>>(bias);
  recurrence<<<RNC, RTPB, rec_smem>>>(z, Wh, out, hlast);
}